// round 11
// baseline (speedup 1.0000x reference)
#include <cuda_runtime.h>
#include <stdint.h>

// Problem constants
#define BATCH        8
#define DOF          300000
#define NFIX         3000
#define NEWTON_ITERS 6
#define D4           (DOF / 4)            // 75000 float4 per batch row
#define BX           19                   // blocks per batch row
#define TPB          1024
#define STRIDE       (BX * TPB)           // 19456 float4-threads per batch row
#define CHUNKS       4                    // 4*19456 = 77824 >= 75000
#define D4P          (CHUNKS * STRIDE)    // 77824 padded float4 per batch row
#define NMON         6                    // GG, PP, QQ, GP, GQ, PQ (GP/GQ sign-flipped)
#define NP2          (2 * CHUNKS)         // 8 packed f32x2 values per thread
#define NWARP        (TPB / 32)

// Grid = 152 blocks = one per GB300 SM; all co-resident -> no barrier deadlock.

// alphas[t] = max(0.5^t, 0.05)
__constant__ float c_alpha[8] = {1.0f, 0.5f, 0.25f, 0.125f, 0.0625f, 0.05f, 0.05f, 0.05f};

// Packed constants: (0.4f,0.4f) and (1.2f,1.2f)
#define C04 0x3ECCCCCD3ECCCCCDull
#define C12 0x3F99999A3F99999Aull

// Device scratch (allocation-free).
// g_fm: packed (-f), masked to 0 at fixed dofs and padded-tail slots. Per batch.
// g_km: packed k, masked to 1 at fixed dofs / tails. Shared across batches
//       (blocks with equal bx write identical values -> benign).
// Each block writes ONLY its own slice and reads ONLY its own slice, so the
// one-time setup needs no inter-block sync; rewrites on graph replay are
// identical -> deterministic.
__device__ ulonglong2 g_fm[BATCH * D4P];
__device__ ulonglong2 g_km[D4P];
// g_sum / g_cnt: 3-buffer rotation + deferred-reset counters, replay-safe
// (same protocol as previous round; see comments at use sites).
__device__ float g_sum[3][NMON * BATCH];
__device__ int   g_cnt[NEWTON_ITERS][BATCH];

// ---- packed f32x2 helpers -------------------------------------------------
__device__ __forceinline__ uint64_t fma2(uint64_t a, uint64_t b, uint64_t c)
{
    uint64_t d;
    asm("fma.rn.f32x2 %0, %1, %2, %3;" : "=l"(d) : "l"(a), "l"(b), "l"(c));
    return d;
}
__device__ __forceinline__ uint64_t mul2(uint64_t a, uint64_t b)
{
    uint64_t d;
    asm("mul.rn.f32x2 %0, %1, %2;" : "=l"(d) : "l"(a), "l"(b));
    return d;
}
__device__ __forceinline__ uint64_t pack2(float lo, float hi)
{
    uint64_t d;
    asm("mov.b64 %0, {%1, %2};" : "=l"(d) : "f"(lo), "f"(hi));
    return d;
}
__device__ __forceinline__ void unpack2(uint64_t v, float& lo, float& hi)
{
    asm("mov.b64 {%0, %1}, %2;" : "=f"(lo), "=f"(hi) : "l"(v));
}
__device__ __forceinline__ uint64_t rcp2(uint64_t h)
{
    float lo, hi;
    unpack2(h, lo, hi);
    float rl, rh;
    asm("rcp.approx.f32 %0, %1;" : "=f"(rl) : "f"(lo));
    asm("rcp.approx.f32 %0, %1;" : "=f"(rh) : "f"(hi));
    return pack2(rl, rh);
}
// ---- sync helpers ----------------------------------------------------------
__device__ __forceinline__ void redAddRelaxedF32(float* a, float v)
{
    asm volatile("red.relaxed.gpu.global.add.f32 [%0], %1;" :: "l"(a), "f"(v) : "memory");
}
__device__ __forceinline__ void redAddReleaseS32(int* a, int v)
{
    asm volatile("red.release.gpu.global.add.s32 [%0], %1;" :: "l"(a), "r"(v) : "memory");
}
__device__ __forceinline__ int ldAcquireS32(const int* a)
{
    int v;
    asm volatile("ld.acquire.gpu.global.s32 %0, [%1];" : "=r"(v) : "l"(a) : "memory");
    return v;
}

// ---------------------------------------------------------------------------
// Per-pair hot math, all packed f32x2 (2 elements per op):
//   g' = u*(k+0.4u^2) - f  (= -g; inputs pre-negated/masked so no mask ops)
//   h  = k + 1.2u^2 ;  du = g' * rcp(h)  (= -g/h)
//   P  = u*du^2 ; Q = du^3
//   acc: GG=g'g', PP, QQ, (−GP)=g'P, (−GQ)=g'Q, PQ
__device__ __forceinline__ void mathPair(uint64_t u, uint64_t fneg, uint64_t k,
                                         uint64_t* duslot, uint64_t acc[NMON])
{
    uint64_t u2 = mul2(u, u);
    uint64_t t  = fma2(C04, u2, k);
    uint64_t h  = fma2(C12, u2, k);
    uint64_t gp = fma2(u, t, fneg);
    uint64_t r  = rcp2(h);
    uint64_t v  = mul2(gp, r);
    *duslot = v;
    uint64_t v2 = mul2(v, v);
    uint64_t P  = mul2(u, v2);
    uint64_t Q  = mul2(v, v2);
    acc[0] = fma2(gp, gp, acc[0]);
    acc[1] = fma2(P,  P,  acc[1]);
    acc[2] = fma2(Q,  Q,  acc[2]);
    acc[3] = fma2(gp, P,  acc[3]);
    acc[4] = fma2(gp, Q,  acc[4]);
    acc[5] = fma2(P,  Q,  acc[5]);
}

// ---------------------------------------------------------------------------
__global__ void __launch_bounds__(TPB, 1)
kSolve(const float* __restrict__ f,
       const float* __restrict__ u0,
       const float* __restrict__ kd,
       const int*   __restrict__ fixed_dofs,
       float* __restrict__ out)
{
    const int tid = threadIdx.x;
    const int bx  = blockIdx.x;
    const int b   = blockIdx.y;
    const int i0  = bx * TPB + tid;

    const float4* f4 = reinterpret_cast<const float4*>(f) + (size_t)b * D4;
    const float4* k4 = reinterpret_cast<const float4*>(kd);
    const float4* u4 = reinterpret_cast<const float4*>(u0) + (size_t)b * D4;

    // dynamic shared memory partition
    extern __shared__ char smraw[];
    uint64_t* du_s   = reinterpret_cast<uint64_t*>(smraw);                 // NP2*TPB u64 = 64KB
    uint32_t* maskw  = reinterpret_cast<uint32_t*>(smraw + NP2 * TPB * 8); // 512 words
    float*    sred   = reinterpret_cast<float*>(maskw + CHUNKS * (TPB / 8)); // NWARP*NMON
    float*    s_alph = sred + NWARP * NMON;

    // ---- build this block's fixed-dof bitmap (once) ----
    for (int j = tid; j < CHUNKS * (TPB / 8); j += TPB) maskw[j] = 0u;
    __syncthreads();
    for (int j = tid; j < NFIX; j += TPB) {
        int d = fixed_dofs[j];
#pragma unroll
        for (int c = 0; c < CHUNKS; c++) {
            int lo = (bx * TPB + c * STRIDE) * 4;
            unsigned off = (unsigned)(d - lo);
            if (off < (unsigned)(TPB * 4))
                atomicOr(&maskw[c * (TPB / 8) + (off >> 5)], 1u << (off & 31));
        }
    }
    __syncthreads();

    // ---- setup: masked u -> registers; (-f,k) masked -> padded scratch ----
    uint32_t nibs = 0;
    uint64_t up[NP2];
#pragma unroll
    for (int c = 0; c < CHUNKS; c++) {
        int i  = i0 + c * STRIDE;           // padded index, unique per (b,thread)
        int ic = (i < D4) ? i : (D4 - 1);
        float4 uu = u4[ic];
        float4 ff = f4[ic];
        float4 kk = k4[ic];
        uint32_t w  = maskw[c * (TPB / 8) + (tid >> 3)];
        uint32_t nb = (w >> ((tid & 7) * 4)) & 0xFu;
        if (i >= D4) nb = 0xFu;
        nibs |= nb << (c * 4);

        float ua[4] = {uu.x, uu.y, uu.z, uu.w};
        float fa[4] = {ff.x, ff.y, ff.z, ff.w};
        float ka[4] = {kk.x, kk.y, kk.z, kk.w};
        float ul[4], fm[4], km[4];
#pragma unroll
        for (int j = 0; j < 4; j++) {
            bool fx = (nb >> j) & 1u;
            ul[j] = fx ? 0.0f : ua[j];
            fm[j] = fx ? 0.0f : -fa[j];
            km[j] = fx ? 1.0f : ka[j];
        }
        up[2 * c + 0] = pack2(ul[0], ul[1]);
        up[2 * c + 1] = pack2(ul[2], ul[3]);
        ulonglong2 pf; pf.x = pack2(fm[0], fm[1]); pf.y = pack2(fm[2], fm[3]);
        ulonglong2 pk; pk.x = pack2(km[0], km[1]); pk.y = pack2(km[2], km[3]);
        g_fm[(size_t)b * D4P + i] = pf;     // own slice only
        g_km[i] = pk;                        // identical dup across b: benign
    }

    for (int it = 0; it < NEWTON_ITERS; it++) {
        uint64_t acc[NMON];
#pragma unroll
        for (int m = 0; m < NMON; m++) acc[m] = 0ull;

        // ---- compute phase: packed f32x2, no masks, du -> own smem column --
#pragma unroll
        for (int c = 0; c < CHUNKS; c++) {
            int i = i0 + c * STRIDE;
            ulonglong2 fp = g_fm[(size_t)b * D4P + i];
            ulonglong2 kp = g_km[i];
            mathPair(up[2 * c + 0], fp.x, kp.x, &du_s[(2 * c + 0) * TPB + tid], acc);
            mathPair(up[2 * c + 1], fp.y, kp.y, &du_s[(2 * c + 1) * TPB + tid], acc);
        }

        // ---- deterministic block reduction (halves summed first) ----
        float sa[NMON];
#pragma unroll
        for (int m = 0; m < NMON; m++) {
            float lo, hi; unpack2(acc[m], lo, hi);
            sa[m] = lo + hi;
#pragma unroll
            for (int o = 16; o; o >>= 1)
                sa[m] += __shfl_down_sync(0xffffffffu, sa[m], o);
        }
        if ((tid & 31) == 0) {
            int w = tid >> 5;
#pragma unroll
            for (int m = 0; m < NMON; m++) sred[w * NMON + m] = sa[m];
        }
        __syncthreads();
        const int buf = it % 3;
        if (tid < NMON) {
            float s = 0.0f;
#pragma unroll
            for (int w = 0; w < NWARP; w++) s += sred[w * NMON + tid];
            redAddRelaxedF32(&g_sum[buf][tid * BATCH + b], s);
        }
        __syncthreads();

        // ---- per-batch barrier: release arrive, acquire poll + backoff ----
        if (tid == 0) {
            redAddReleaseS32(&g_cnt[it][b], 1);
            while (ldAcquireS32(&g_cnt[it][b]) < BX) __nanosleep(64);
        }
        __syncthreads();

        // ---- alpha (note: acc3/acc4 hold -GP/-GQ -> sign-corrected) ----
        if (tid == 0) {
            const float* S = &g_sum[buf][0];
            float gg  = __ldcg(&S[0 * BATCH + b]);
            float pp  = __ldcg(&S[1 * BATCH + b]);
            float qq  = __ldcg(&S[2 * BATCH + b]);
            float gpn = __ldcg(&S[3 * BATCH + b]);   // = -GP
            float gqn = __ldcg(&S[4 * BATCH + b]);   // = -GQ
            float pq  = __ldcg(&S[5 * BATCH + b]);
            float a = 0.05f;                 // ALPHA_MIN
#pragma unroll
            for (int tr = 7; tr >= 0; tr--) {
                float at = c_alpha[tr];
                float c1 = 1.0f + at;
                float c2 = -1.2f * at * at;
                float c3 = -0.4f * at * at * at;
                float n2 = c1 * c1 * gg + c2 * c2 * pp + c3 * c3 * qq
                         + 2.0f * (-c1 * c2 * gpn - c1 * c3 * gqn + c2 * c3 * pq);
                if (n2 < gg) a = at;         // downward scan -> first improving
            }
            *s_alph = a;
        }

        // housekeeping off the critical path: reset old counter, zero the
        // it+2 sum buffer. Release-ordered by this block's arrival at it+1.
        if (bx == 0 && tid == 32) {
            int prev = (it == 0) ? (NEWTON_ITERS - 1) : (it - 1);
            __stcg(&g_cnt[prev][b], 0);
            float* z = &g_sum[(it + 2) % 3][0];
#pragma unroll
            for (int m = 0; m < NMON; m++) __stcg(&z[m * BATCH + b], 0.0f);
        }
        __syncthreads();

        // ---- update: u += alpha * du (packed; own smem column) ----
        uint64_t A2 = pack2(*s_alph, *s_alph);
#pragma unroll
        for (int x = 0; x < NP2; x++)
            up[x] = fma2(A2, du_s[x * TPB + tid], up[x]);
    }

    // ---- final store: restore u0 at fixed lanes, skip padded tails ----
    float4* o4 = reinterpret_cast<float4*>(out) + (size_t)b * D4;
#pragma unroll
    for (int c = 0; c < CHUNKS; c++) {
        int i = i0 + c * STRIDE;
        if (i < D4) {
            uint32_t nb = (nibs >> (c * 4)) & 0xFu;
            float4 uu = u4[i];
            float r0, r1, r2, r3;
            unpack2(up[2 * c + 0], r0, r1);
            unpack2(up[2 * c + 1], r2, r3);
            float4 o;
            o.x = (nb & 1u) ? uu.x : r0;
            o.y = (nb & 2u) ? uu.y : r1;
            o.z = (nb & 4u) ? uu.z : r2;
            o.w = (nb & 8u) ? uu.w : r3;
            o4[i] = o;
        }
    }
}

// ---------------------------------------------------------------------------
extern "C" void kernel_launch(void* const* d_in, const int* in_sizes, int n_in,
                              void* d_out, int out_size)
{
    const float* f  = (const float*)d_in[0];   // external_forces [B, DOF]
    const float* u0 = (const float*)d_in[1];   // u0              [B, DOF]
    const float* kd = (const float*)d_in[2];   // k_diag          [DOF]
    const int*   fd = (const int*)d_in[3];     // fixed_dofs      [NFIX]

    const size_t smem = (size_t)NP2 * TPB * 8                 // du_s (64KB)
                      + (size_t)CHUNKS * (TPB / 8) * 4        // maskw
                      + (size_t)NWARP * NMON * 4              // sred
                      + 16;                                   // s_alpha + pad
    static int configured = 0;
    if (!configured) {
        cudaFuncSetAttribute(kSolve, cudaFuncAttributeMaxDynamicSharedMemorySize,
                             (int)smem);
        configured = 1;
    }
    kSolve<<<dim3(BX, BATCH), TPB, smem>>>(f, u0, kd, fd, (float*)d_out);
}